// round 3
// baseline (speedup 1.0000x reference)
#include <cuda_runtime.h>
#include <math.h>

#define VOCAB 50000
#define D 256
#define E_EDGES 4096
#define S_SEQ 9
#define NUM_ORDERS 3

// ---------------- scratch (device globals: allocation-free) ----------------
__device__ float g_var0[E_EDGES * D];
__device__ float g_var1[E_EDGES * D];
__device__ float g_h[E_EDGES * D];       // LN output, later reused as enc
__device__ float g_hidden[E_EDGES * D];
__device__ float g_tmpC[E_EDGES * D];
__device__ float g_tmpD[E_EDGES * D];
__device__ float g_rowloss[E_EDGES];

// ---------------- init vars to 1.0 ----------------
__global__ void k_init(float* __restrict__ v0, float* __restrict__ v1) {
    int i = blockIdx.x * 256 + threadIdx.x;
    v0[i] = 1.0f;
    v1[i] = 1.0f;
}

// ---------------- encoder stage 1: gather + masked pool + out-token + LN ----------------
__global__ void k_encoder(const float* __restrict__ node_emb,
                          const int* __restrict__ input_ids,
                          const float* __restrict__ input_mask,
                          const int* __restrict__ var_in_mask,
                          const int* __restrict__ var_in_batch,
                          const int* __restrict__ out_pos,
                          const float* __restrict__ ln_g,
                          const float* __restrict__ ln_b,
                          const float* __restrict__ var1,
                          float* __restrict__ h) {
    int e = blockIdx.x;
    int d = threadIdx.x;
    int op = out_pos[e];

    float acc = 0.0f, msum = 0.0f, outv = 0.0f;
#pragma unroll
    for (int s = 0; s < S_SEQ; s++) {
        int idx = s * E_EDGES + e;
        float m = input_mask[idx];
        float val;
        if (var_in_mask[idx] >= 0) {
            int j = var_in_batch[idx];
            j = max(0, min(E_EDGES - 1, j));
            val = var1[j * D + d];
        } else {
            val = node_emb[(long long)input_ids[idx] * D + d];
        }
        acc += val * m;
        msum += m;
        if (s == op) outv = val;
    }
    float x = acc / fmaxf(msum, 1.0f) + outv;

    // layernorm over D=256 (8 warps)
    float v1s = x, v2s = x * x;
#pragma unroll
    for (int o = 16; o > 0; o >>= 1) {
        v1s += __shfl_down_sync(0xFFFFFFFFu, v1s, o);
        v2s += __shfl_down_sync(0xFFFFFFFFu, v2s, o);
    }
    __shared__ float red1[8], red2[8];
    int wid = d >> 5, lane = d & 31;
    if (lane == 0) { red1[wid] = v1s; red2[wid] = v2s; }
    __syncthreads();
    float tot1 = 0.0f, tot2 = 0.0f;
#pragma unroll
    for (int i = 0; i < 8; i++) { tot1 += red1[i]; tot2 += red2[i]; }
    float mu = tot1 * (1.0f / D);
    float var = tot2 * (1.0f / D) - mu * mu;
    float y = (x - mu) * rsqrtf(var + 1e-5f) * ln_g[d] + ln_b[d];
    h[e * D + d] = y;
}

// ---------------- MLP GEMM: C = act(A[4096,256] @ W[256,256] + bias) ----------------
// 16 rows per block, 256 threads (one column each), k-unroll 8
__global__ void k_mlp(const float* __restrict__ A, const float* __restrict__ W,
                      const float* __restrict__ bias, float* __restrict__ C,
                      int mode /*0=relu 1=sigmoid*/) {
    __shared__ __align__(16) float sA[16][D];
    int r0 = blockIdx.x * 16;
    // load 16x256 tile (1024 float4)
    const float4* src = (const float4*)(A + (size_t)r0 * D);
    float4* dst = (float4*)&sA[0][0];
    for (int i = threadIdx.x; i < 16 * (D / 4); i += 256) dst[i] = src[i];
    __syncthreads();

    int j = threadIdx.x;
    float acc[16];
#pragma unroll
    for (int r = 0; r < 16; r++) acc[r] = 0.0f;

    for (int k = 0; k < D; k += 8) {
        float w[8];
#pragma unroll
        for (int u = 0; u < 8; u++) w[u] = W[(k + u) * D + j];
#pragma unroll
        for (int r = 0; r < 16; r++) {
            float4 a0 = *(const float4*)&sA[r][k];
            float4 a1 = *(const float4*)&sA[r][k + 4];
            acc[r] += a0.x * w[0] + a0.y * w[1] + a0.z * w[2] + a0.w * w[3]
                    + a1.x * w[4] + a1.y * w[5] + a1.z * w[6] + a1.w * w[7];
        }
    }
    float b = bias[j];
#pragma unroll
    for (int r = 0; r < 16; r++) {
        float v = acc[r] + b;
        if (mode == 0) v = fmaxf(v, 0.0f);
        else v = 1.0f / (1.0f + __expf(-v));
        C[(size_t)(r0 + r) * D + j] = v;
    }
}

// ---------------- var update (+negation) for current-order edges ----------------
__global__ void k_update(const float* __restrict__ enc,
                         const int* __restrict__ orders,
                         const int* __restrict__ types, int order,
                         float* __restrict__ var0, float* __restrict__ var1) {
    int e = blockIdx.x;
    if (orders[e] != order) return;
    int d = threadIdx.x;
    float v = enc[e * D + d];
    var0[e * D + d] = v;
    var1[e * D + d] = (types[e] == 1) ? (1.0f - v) : v;
}

// ---------------- conjunction: prod over valid fan-in, basis[0]=var0 ----------------
__global__ void k_conj(const float* __restrict__ var0, const float* __restrict__ var1,
                       const int* __restrict__ orders, const int* __restrict__ types,
                       const int* __restrict__ lin, const int* __restrict__ lib,
                       int order, float* __restrict__ tmpC) {
    int e = blockIdx.x;
    if (orders[e] != order || types[e] != 2) return;
    int d = threadIdx.x;
    float p = var0[e * D + d];
#pragma unroll
    for (int a = 1; a < 4; a++) {
        if (lin[a * E_EDGES + e] >= 0) {
            int j = lib[a * E_EDGES + e];
            j = max(0, min(E_EDGES - 1, j));
            p *= var1[j * D + d];
        }
    }
    tmpC[e * D + d] = p;
}

// ---------------- disjunction: 1 - prod(1 - basis), sees post-conj var1 via tmpC redirect ----------------
__global__ void k_disj(const float* __restrict__ var0, const float* __restrict__ var1,
                       const int* __restrict__ orders, const int* __restrict__ types,
                       const int* __restrict__ lin, const int* __restrict__ lib,
                       int order, const float* __restrict__ tmpC, float* __restrict__ tmpD) {
    int e = blockIdx.x;
    if (orders[e] != order || types[e] != 3) return;
    int d = threadIdx.x;
    float q = 1.0f - var0[e * D + d];
#pragma unroll
    for (int a = 1; a < 4; a++) {
        if (lin[a * E_EDGES + e] >= 0) {
            int j = lib[a * E_EDGES + e];
            j = max(0, min(E_EDGES - 1, j));
            float v = (orders[j] == order && types[j] == 2) ? tmpC[j * D + d]
                                                           : var1[j * D + d];
            q *= (1.0f - v);
        }
    }
    tmpD[e * D + d] = 1.0f - q;
}

// ---------------- apply conj/disj results ----------------
__global__ void k_apply(const int* __restrict__ orders, const int* __restrict__ types,
                        int order, const float* __restrict__ tmpC,
                        const float* __restrict__ tmpD, float* __restrict__ var1) {
    int e = blockIdx.x;
    if (orders[e] != order) return;
    int ty = types[e];
    int d = threadIdx.x;
    if (ty == 2) var1[e * D + d] = tmpC[e * D + d];
    else if (ty == 3) var1[e * D + d] = tmpD[e * D + d];
}

// ---------------- vocab GEMM: C[4096,50000] = var1[4096,256] @ node_emb[50000,256]^T ----------------
#define BM 64
#define BN 64
#define BK 16
__global__ void k_gemm_nt(const float* __restrict__ A, const float* __restrict__ B,
                          float* __restrict__ C) {
    __shared__ __align__(16) float sA[BK][BM];
    __shared__ __align__(16) float sB[BK][BN];
    int bm = blockIdx.y * BM;
    int bn = blockIdx.x * BN;
    int tid = threadIdx.x;
    int tx = tid & 15, ty = tid >> 4;

    float acc[4][4];
#pragma unroll
    for (int i = 0; i < 4; i++)
#pragma unroll
        for (int jj = 0; jj < 4; jj++) acc[i][jj] = 0.0f;

    int lr = tid >> 2;          // 0..63 tile row
    int lk = (tid & 3) * 4;     // 0,4,8,12 within BK

    for (int k0 = 0; k0 < D; k0 += BK) {
        float4 av = *(const float4*)(A + (size_t)(bm + lr) * D + k0 + lk);
        int brow = bn + lr;
        float4 bv = make_float4(0.f, 0.f, 0.f, 0.f);
        if (brow < VOCAB) bv = *(const float4*)(B + (size_t)brow * D + k0 + lk);
        __syncthreads();
        sA[lk + 0][lr] = av.x; sA[lk + 1][lr] = av.y;
        sA[lk + 2][lr] = av.z; sA[lk + 3][lr] = av.w;
        sB[lk + 0][lr] = bv.x; sB[lk + 1][lr] = bv.y;
        sB[lk + 2][lr] = bv.z; sB[lk + 3][lr] = bv.w;
        __syncthreads();
#pragma unroll
        for (int k = 0; k < BK; k++) {
            float4 a = *(const float4*)&sA[k][ty * 4];
            float4 b = *(const float4*)&sB[k][tx * 4];
            acc[0][0] += a.x * b.x; acc[0][1] += a.x * b.y; acc[0][2] += a.x * b.z; acc[0][3] += a.x * b.w;
            acc[1][0] += a.y * b.x; acc[1][1] += a.y * b.y; acc[1][2] += a.y * b.z; acc[1][3] += a.y * b.w;
            acc[2][0] += a.z * b.x; acc[2][1] += a.z * b.y; acc[2][2] += a.z * b.z; acc[2][3] += a.z * b.w;
            acc[3][0] += a.w * b.x; acc[3][1] += a.w * b.y; acc[3][2] += a.w * b.z; acc[3][3] += a.w * b.w;
        }
    }
#pragma unroll
    for (int i = 0; i < 4; i++) {
        int row = bm + ty * 4 + i;
#pragma unroll
        for (int jj = 0; jj < 4; jj++) {
            int col = bn + tx * 4 + jj;
            if (col < VOCAB) C[(size_t)row * VOCAB + col] = acc[i][jj];
        }
    }
}

// ---------------- per-row soft-label CE via online logsumexp ----------------
__global__ void k_rowloss(const float* __restrict__ logits,
                          const int* __restrict__ answers,
                          const int* __restrict__ mask_type,
                          float* __restrict__ rowloss) {
    int e = blockIdx.x;
    const float* row = logits + (size_t)e * VOCAB;
    int t = threadIdx.x;
    float m = -1e30f, s = 0.0f, sx = 0.0f;
    for (int v = t; v < VOCAB; v += 256) {
        float x = row[v];
        sx += x;
        float mn = fmaxf(m, x);
        s = s * __expf(m - mn) + __expf(x - mn);
        m = mn;
    }
    __shared__ float shm[256], shs[256], shx[256];
    shm[t] = m; shs[t] = s; shx[t] = sx;
    __syncthreads();
    for (int off = 128; off > 0; off >>= 1) {
        if (t < off) {
            float m2 = shm[t + off], s2 = shs[t + off];
            float mn = fmaxf(shm[t], m2);
            shs[t] = shs[t] * __expf(shm[t] - mn) + s2 * __expf(m2 - mn);
            shm[t] = mn;
            shx[t] += shx[t + off];
        }
        __syncthreads();
    }
    if (t == 0) {
        float lse = shm[0] + logf(shs[0]);
        float sumx = shx[0];
        float la = row[answers[e]] - lse;
        float soft = (mask_type[e] > 0) ? 0.9f : 1.0f;
        float loss = -(soft * la +
                       (1.0f - soft) * (1.0f / (float)(VOCAB - 1)) *
                           ((sumx - (float)VOCAB * lse) - la));
        rowloss[e] = loss;
    }
}

__global__ void k_finalloss(const float* __restrict__ rowloss, float* __restrict__ out) {
    __shared__ float sh[256];
    float a = 0.0f;
    for (int i = threadIdx.x; i < E_EDGES; i += 256) a += rowloss[i];
    sh[threadIdx.x] = a;
    __syncthreads();
    for (int off = 128; off > 0; off >>= 1) {
        if (threadIdx.x < off) sh[threadIdx.x] += sh[threadIdx.x + off];
        __syncthreads();
    }
    if (threadIdx.x == 0) out[0] = sh[0] * (1.0f / (float)E_EDGES);
}

// ---------------- launch ----------------
extern "C" void kernel_launch(void* const* d_in, const int* in_sizes, int n_in,
                              void* d_out, int out_size) {
    const float* node_emb   = (const float*)d_in[0];
    const int*   input_ids  = (const int*)d_in[1];
    const float* input_mask = (const float*)d_in[2];
    const int*   edge_ord   = (const int*)d_in[3];
    const int*   vim        = (const int*)d_in[4];
    const int*   vibm       = (const int*)d_in[5];
    const int*   out_pos    = (const int*)d_in[6];
    const int*   lin        = (const int*)d_in[7];
    const int*   lib        = (const int*)d_in[8];
    const int*   ltypes     = (const int*)d_in[9];
    const int*   answers    = (const int*)d_in[10];
    const int*   mask_type  = (const int*)d_in[11];
    const float* W1         = (const float*)d_in[12];
    const float* b1         = (const float*)d_in[13];
    const float* W2         = (const float*)d_in[14];
    const float* b2         = (const float*)d_in[15];
    const float* ln_g       = (const float*)d_in[16];
    const float* ln_b       = (const float*)d_in[17];

    float* out = (float*)d_out;
    long long loff = (long long)out_size - (long long)E_EDGES * VOCAB;
    if (loff < 0) loff = 0;
    float* logits = out + loff;   // loss (if present) sits at out[0]

    float *var0, *var1, *h, *hidden, *tmpC, *tmpD, *rowloss;
    cudaGetSymbolAddress((void**)&var0, g_var0);
    cudaGetSymbolAddress((void**)&var1, g_var1);
    cudaGetSymbolAddress((void**)&h, g_h);
    cudaGetSymbolAddress((void**)&hidden, g_hidden);
    cudaGetSymbolAddress((void**)&tmpC, g_tmpC);
    cudaGetSymbolAddress((void**)&tmpD, g_tmpD);
    cudaGetSymbolAddress((void**)&rowloss, g_rowloss);

    k_init<<<(E_EDGES * D) / 256, 256>>>(var0, var1);

    for (int order = 0; order < NUM_ORDERS; ++order) {
        k_encoder<<<E_EDGES, 256>>>(node_emb, input_ids, input_mask, vim, vibm,
                                    out_pos, ln_g, ln_b, var1, h);
        k_mlp<<<E_EDGES / 16, 256>>>(h, W1, b1, hidden, 0);
        k_mlp<<<E_EDGES / 16, 256>>>(hidden, W2, b2, h, 1);  // h := enc
        k_update<<<E_EDGES, 256>>>(h, edge_ord, ltypes, order, var0, var1);
        k_conj<<<E_EDGES, 256>>>(var0, var1, edge_ord, ltypes, lin, lib, order, tmpC);
        k_disj<<<E_EDGES, 256>>>(var0, var1, edge_ord, ltypes, lin, lib, order, tmpC, tmpD);
        k_apply<<<E_EDGES, 256>>>(edge_ord, ltypes, order, tmpC, tmpD, var1);
    }

    dim3 grid((VOCAB + BN - 1) / BN, E_EDGES / BM);
    k_gemm_nt<<<grid, 256>>>(var1, node_emb, logits);

    if (loff >= 1) {
        k_rowloss<<<E_EDGES, 256>>>(logits, answers, mask_type, rowloss);
        k_finalloss<<<1, 256>>>(rowloss, out);
    }
}

// round 9
// speedup vs baseline: 2.5206x; 2.5206x over previous
#include <cuda_runtime.h>
#include <cuda_bf16.h>
#include <math.h>
#include <stdint.h>

#define VOCAB 50000
#define D 256
#define E_EDGES 4096
#define S_SEQ 9
#define NUM_ORDERS 3

// ---------------- scratch (device globals: allocation-free) ----------------
__device__ __align__(256) float g_var0[E_EDGES * D];
__device__ __align__(256) float g_var1[E_EDGES * D];
__device__ __align__(256) float g_h[E_EDGES * D];
__device__ __align__(256) float g_hidden[E_EDGES * D];
__device__ __align__(256) float g_tmpC[E_EDGES * D];
__device__ __align__(256) float g_tmpD[E_EDGES * D];
__device__ __align__(256) float g_rowloss[E_EDGES];
// bf16 hi/lo splits for the vocab GEMM
__device__ __align__(256) __nv_bfloat16 g_Ahi[E_EDGES * D];
__device__ __align__(256) __nv_bfloat16 g_Alo[E_EDGES * D];
__device__ __align__(256) __nv_bfloat16 g_Bhi[VOCAB * D];
__device__ __align__(256) __nv_bfloat16 g_Blo[VOCAB * D];

// ---------------- helpers ----------------
__device__ __forceinline__ uint32_t smem_u32(const void* p) {
    uint32_t a;
    asm("{ .reg .u64 t; cvta.to.shared.u64 t, %1; cvt.u32.u64 %0, t; }"
        : "=r"(a) : "l"(p));
    return a;
}
__device__ __forceinline__ void cpa16(uint32_t saddr, const void* gptr, uint32_t ssize) {
    unsigned long long g = __cvta_generic_to_global(const_cast<void*>(gptr));
    asm volatile("cp.async.cg.shared.global [%0], [%1], 16, %2;"
                 :: "r"(saddr), "l"(g), "r"(ssize));
}
__device__ __forceinline__ void mma16816(float* c, const uint32_t* a, const uint32_t* b) {
    asm volatile("mma.sync.aligned.m16n8k16.row.col.f32.bf16.bf16.f32 "
                 "{%0,%1,%2,%3}, {%4,%5,%6,%7}, {%8,%9}, {%0,%1,%2,%3};"
                 : "+f"(c[0]), "+f"(c[1]), "+f"(c[2]), "+f"(c[3])
                 : "r"(a[0]), "r"(a[1]), "r"(a[2]), "r"(a[3]), "r"(b[0]), "r"(b[1]));
}
__device__ __forceinline__ void ldsm_x4(uint32_t* r, uint32_t addr) {
    asm volatile("ldmatrix.sync.aligned.m8n8.x4.shared.b16 {%0,%1,%2,%3}, [%4];"
                 : "=r"(r[0]), "=r"(r[1]), "=r"(r[2]), "=r"(r[3]) : "r"(addr));
}
__device__ __forceinline__ void ldsm_x2(uint32_t* r, uint32_t addr) {
    asm volatile("ldmatrix.sync.aligned.m8n8.x2.shared.b16 {%0,%1}, [%2];"
                 : "=r"(r[0]), "=r"(r[1]) : "r"(addr));
}

// ---------------- init vars to 1.0 ----------------
__global__ void k_init(float* __restrict__ v0, float* __restrict__ v1) {
    int i = blockIdx.x * 256 + threadIdx.x;
    v0[i] = 1.0f;
    v1[i] = 1.0f;
}

// ---------------- hi/lo bf16 split ----------------
__global__ void k_split(const float* __restrict__ x, __nv_bfloat16* __restrict__ hi,
                        __nv_bfloat16* __restrict__ lo, int n) {
    int i = blockIdx.x * 256 + threadIdx.x;
    if (i < n) {
        float v = x[i];
        __nv_bfloat16 h = __float2bfloat16(v);
        hi[i] = h;
        lo[i] = __float2bfloat16(v - __bfloat162float(h));
    }
}

// ---------------- encoder: gather + masked pool + out-token + LN ----------------
__global__ void k_encoder(const float* __restrict__ node_emb,
                          const int* __restrict__ input_ids,
                          const float* __restrict__ input_mask,
                          const int* __restrict__ var_in_mask,
                          const int* __restrict__ var_in_batch,
                          const int* __restrict__ out_pos,
                          const float* __restrict__ ln_g,
                          const float* __restrict__ ln_b,
                          const float* __restrict__ var1,
                          float* __restrict__ h) {
    int e = blockIdx.x;
    int d = threadIdx.x;
    int op = out_pos[e];

    float acc = 0.0f, msum = 0.0f, outv = 0.0f;
#pragma unroll
    for (int s = 0; s < S_SEQ; s++) {
        int idx = s * E_EDGES + e;
        float m = input_mask[idx];
        float val;
        if (var_in_mask[idx] >= 0) {
            int j = var_in_batch[idx];
            j = max(0, min(E_EDGES - 1, j));
            val = var1[j * D + d];
        } else {
            val = node_emb[(long long)input_ids[idx] * D + d];
        }
        acc += val * m;
        msum += m;
        if (s == op) outv = val;
    }
    float x = acc / fmaxf(msum, 1.0f) + outv;

    float v1s = x, v2s = x * x;
#pragma unroll
    for (int o = 16; o > 0; o >>= 1) {
        v1s += __shfl_down_sync(0xFFFFFFFFu, v1s, o);
        v2s += __shfl_down_sync(0xFFFFFFFFu, v2s, o);
    }
    __shared__ float red1[8], red2[8];
    int wid = d >> 5, lane = d & 31;
    if (lane == 0) { red1[wid] = v1s; red2[wid] = v2s; }
    __syncthreads();
    float tot1 = 0.0f, tot2 = 0.0f;
#pragma unroll
    for (int i = 0; i < 8; i++) { tot1 += red1[i]; tot2 += red2[i]; }
    float mu = tot1 * (1.0f / D);
    float var = tot2 * (1.0f / D) - mu * mu;
    float y = (x - mu) * rsqrtf(var + 1e-5f) * ln_g[d] + ln_b[d];
    h[e * D + d] = y;
}

// ---------------- MLP GEMM: C = act(A[4096,256] @ W[256,256] + bias) ----------------
__global__ void k_mlp(const float* __restrict__ A, const float* __restrict__ W,
                      const float* __restrict__ bias, float* __restrict__ C,
                      int mode) {
    __shared__ __align__(16) float sA[16][D];
    int r0 = blockIdx.x * 16;
    const float4* src = (const float4*)(A + (size_t)r0 * D);
    float4* dst = (float4*)&sA[0][0];
    for (int i = threadIdx.x; i < 16 * (D / 4); i += 256) dst[i] = src[i];
    __syncthreads();

    int j = threadIdx.x;
    float acc[16];
#pragma unroll
    for (int r = 0; r < 16; r++) acc[r] = 0.0f;

    for (int k = 0; k < D; k += 8) {
        float w[8];
#pragma unroll
        for (int u = 0; u < 8; u++) w[u] = W[(k + u) * D + j];
#pragma unroll
        for (int r = 0; r < 16; r++) {
            float4 a0 = *(const float4*)&sA[r][k];
            float4 a1 = *(const float4*)&sA[r][k + 4];
            acc[r] += a0.x * w[0] + a0.y * w[1] + a0.z * w[2] + a0.w * w[3]
                    + a1.x * w[4] + a1.y * w[5] + a1.z * w[6] + a1.w * w[7];
        }
    }
    float b = bias[j];
#pragma unroll
    for (int r = 0; r < 16; r++) {
        float v = acc[r] + b;
        if (mode == 0) v = fmaxf(v, 0.0f);
        else v = 1.0f / (1.0f + __expf(-v));
        C[(size_t)(r0 + r) * D + j] = v;
    }
}

// ---------------- var update (+negation) ----------------
__global__ void k_update(const float* __restrict__ enc,
                         const int* __restrict__ orders,
                         const int* __restrict__ types, int order,
                         float* __restrict__ var0, float* __restrict__ var1) {
    int e = blockIdx.x;
    if (orders[e] != order) return;
    int d = threadIdx.x;
    float v = enc[e * D + d];
    var0[e * D + d] = v;
    var1[e * D + d] = (types[e] == 1) ? (1.0f - v) : v;
}

// ---------------- conjunction ----------------
__global__ void k_conj(const float* __restrict__ var0, const float* __restrict__ var1,
                       const int* __restrict__ orders, const int* __restrict__ types,
                       const int* __restrict__ lin, const int* __restrict__ lib,
                       int order, float* __restrict__ tmpC) {
    int e = blockIdx.x;
    if (orders[e] != order || types[e] != 2) return;
    int d = threadIdx.x;
    float p = var0[e * D + d];
#pragma unroll
    for (int a = 1; a < 4; a++) {
        if (lin[a * E_EDGES + e] >= 0) {
            int j = lib[a * E_EDGES + e];
            j = max(0, min(E_EDGES - 1, j));
            p *= var1[j * D + d];
        }
    }
    tmpC[e * D + d] = p;
}

// ---------------- disjunction (sees post-conj var1 via tmpC redirect) ----------------
__global__ void k_disj(const float* __restrict__ var0, const float* __restrict__ var1,
                       const int* __restrict__ orders, const int* __restrict__ types,
                       const int* __restrict__ lin, const int* __restrict__ lib,
                       int order, const float* __restrict__ tmpC, float* __restrict__ tmpD) {
    int e = blockIdx.x;
    if (orders[e] != order || types[e] != 3) return;
    int d = threadIdx.x;
    float q = 1.0f - var0[e * D + d];
#pragma unroll
    for (int a = 1; a < 4; a++) {
        if (lin[a * E_EDGES + e] >= 0) {
            int j = lib[a * E_EDGES + e];
            j = max(0, min(E_EDGES - 1, j));
            float v = (orders[j] == order && types[j] == 2) ? tmpC[j * D + d]
                                                           : var1[j * D + d];
            q *= (1.0f - v);
        }
    }
    tmpD[e * D + d] = 1.0f - q;
}

// ---------------- apply conj/disj ----------------
__global__ void k_apply(const int* __restrict__ orders, const int* __restrict__ types,
                        int order, const float* __restrict__ tmpC,
                        const float* __restrict__ tmpD, float* __restrict__ var1) {
    int e = blockIdx.x;
    if (orders[e] != order) return;
    int ty = types[e];
    int d = threadIdx.x;
    if (ty == 2) var1[e * D + d] = tmpC[e * D + d];
    else if (ty == 3) var1[e * D + d] = tmpD[e * D + d];
}

// ================= warp-MMA (bf16 HMMA) vocab GEMM =================
// C[4096,50000] = A @ B^T, fp32 via bf16 hi/lo split:
//   C = Ahi*Bhi + Ahi*Blo + Alo*Bhi   (fp32 accumulate)
// NOTE: C (logits) base is only 4-byte aligned (out+1) — scalar stores only!
#define BMT 128
#define BNT 128
#define BKT 64
#define TILE_B (BMT * BKT * 2)       // 16 KB per bf16 tile
#define STAGE_B (4 * TILE_B)         // Ahi,Alo,Bhi,Blo = 64 KB
#define SMEM_GEMM (2 * STAGE_B)      // double buffered = 128 KB

// 128B rows (64 bf16); xor-swizzle 16B chunks for conflict-free ldmatrix
__device__ __forceinline__ uint32_t swz(uint32_t row, uint32_t chunk) {
    return row * 128u + ((chunk ^ (row & 7u)) << 4);
}

__global__ __launch_bounds__(256, 1)
void k_gemm_mma(const __nv_bfloat16* __restrict__ Ahi, const __nv_bfloat16* __restrict__ Alo,
                const __nv_bfloat16* __restrict__ Bhi, const __nv_bfloat16* __restrict__ Blo,
                float* __restrict__ C) {
    extern __shared__ char smem[];
    const int tid = threadIdx.x;
    const int wid = tid >> 5, lane = tid & 31;
    const int bm = blockIdx.y * BMT;
    const int bn = blockIdx.x * BNT;
    const int wm = (wid & 1) * 64;    // warp tile: 64 (m) x 32 (n)
    const int wn = (wid >> 1) * 32;
    const uint32_t sbase = smem_u32(smem);

    float acc[4][4][4];
#pragma unroll
    for (int mt = 0; mt < 4; mt++)
#pragma unroll
        for (int nt = 0; nt < 4; nt++)
#pragma unroll
            for (int q = 0; q < 4; q++) acc[mt][nt][q] = 0.0f;

    // ---- async stage loader: 4 tiles x 1024 chunks, 4 chunks/tile/thread ----
    auto load_stage = [&](int ci, int stg) {
        const int k0 = ci * BKT;
        const uint32_t sst = sbase + (uint32_t)stg * STAGE_B;
#pragma unroll
        for (int j = 0; j < 4; j++) {
            int i = tid + j * 256;
            int row = i >> 3, ch = i & 7;
            uint32_t so = swz(row, ch);
            size_t aoff = (size_t)(bm + row) * D + k0 + ch * 8;
            cpa16(sst + 0 * TILE_B + so, Ahi + aoff, 16);
            cpa16(sst + 1 * TILE_B + so, Alo + aoff, 16);
            int brow = bn + row;
            uint32_t bs = (brow < VOCAB) ? 16u : 0u;
            size_t boff = (size_t)min(brow, VOCAB - 1) * D + k0 + ch * 8;
            cpa16(sst + 2 * TILE_B + so, Bhi + boff, bs);
            cpa16(sst + 3 * TILE_B + so, Blo + boff, bs);
        }
        asm volatile("cp.async.commit_group;" ::: "memory");
    };

    load_stage(0, 0);

    const int jj = lane >> 3;   // quadrant for ldmatrix addressing
    const int rr = lane & 7;

    const int NCH = D / BKT;    // 4
    for (int ci = 0; ci < NCH; ci++) {
        if (ci + 1 < NCH) {
            load_stage(ci + 1, (ci + 1) & 1);
            asm volatile("cp.async.wait_group 1;" ::: "memory");
        } else {
            asm volatile("cp.async.wait_group 0;" ::: "memory");
        }
        __syncthreads();

        const uint32_t sst = sbase + (uint32_t)(ci & 1) * STAGE_B;
#pragma unroll
        for (int kt = 0; kt < 4; kt++) {
            uint32_t a_hi[4][4], a_lo[4][4], b_hi[4][2], b_lo[4][2];
            // A fragments: x4 quadrants (rows g/g+8 x k-lo/k-hi)
            {
                uint32_t arow = (uint32_t)(wm + (jj & 1) * 8 + rr);
                uint32_t ach = (uint32_t)(kt * 2 + (jj >> 1));
#pragma unroll
                for (int mt = 0; mt < 4; mt++) {
                    uint32_t so = swz(arow + mt * 16, ach);
                    ldsm_x4(a_hi[mt], sst + 0 * TILE_B + so);
                    ldsm_x4(a_lo[mt], sst + 1 * TILE_B + so);
                }
            }
            // B fragments: [n][k] rows, x2 (k-lo, k-hi) no-trans
            {
                uint32_t bch = (uint32_t)(kt * 2 + (jj & 1));
#pragma unroll
                for (int nt = 0; nt < 4; nt++) {
                    uint32_t so = swz((uint32_t)(wn + nt * 8 + rr), bch);
                    ldsm_x2(b_hi[nt], sst + 2 * TILE_B + so);
                    ldsm_x2(b_lo[nt], sst + 3 * TILE_B + so);
                }
            }
#pragma unroll
            for (int mt = 0; mt < 4; mt++)
#pragma unroll
                for (int nt = 0; nt < 4; nt++) {
                    mma16816(acc[mt][nt], a_hi[mt], b_hi[nt]);
                    mma16816(acc[mt][nt], a_hi[mt], b_lo[nt]);
                    mma16816(acc[mt][nt], a_lo[mt], b_hi[nt]);
                }
        }
        __syncthreads();
    }

    // ---- epilogue: SCALAR stores (C base is 4B-aligned only: out+1) ----
    const int g = lane >> 2;
    const int qc = (lane & 3) * 2;
#pragma unroll
    for (int mt = 0; mt < 4; mt++) {
        int row0 = bm + wm + mt * 16 + g;
#pragma unroll
        for (int nt = 0; nt < 4; nt++) {
            int col = bn + wn + nt * 8 + qc;
            if (col < VOCAB) {
                float* p0 = &C[(size_t)row0 * VOCAB + col];
                float* p1 = &C[(size_t)(row0 + 8) * VOCAB + col];
                p0[0] = acc[mt][nt][0];
                p0[1] = acc[mt][nt][1];
                p1[0] = acc[mt][nt][2];
                p1[1] = acc[mt][nt][3];
            }
        }
    }
}

// ---------------- per-row soft-label CE via online logsumexp ----------------
__global__ void k_rowloss(const float* __restrict__ logits,
                          const int* __restrict__ answers,
                          const int* __restrict__ mask_type,
                          float* __restrict__ rowloss) {
    int e = blockIdx.x;
    const float* row = logits + (size_t)e * VOCAB;
    int t = threadIdx.x;
    float m = -1e30f, s = 0.0f, sx = 0.0f;
    for (int v = t; v < VOCAB; v += 256) {
        float x = row[v];
        sx += x;
        float mn = fmaxf(m, x);
        s = s * __expf(m - mn) + __expf(x - mn);
        m = mn;
    }
    __shared__ float shm[256], shs[256], shx[256];
    shm[t] = m; shs[t] = s; shx[t] = sx;
    __syncthreads();
    for (int off = 128; off > 0; off >>= 1) {
        if (t < off) {
            float m2 = shm[t + off], s2 = shs[t + off];
            float mn = fmaxf(shm[t], m2);
            shs[t] = shs[t] * __expf(shm[t] - mn) + s2 * __expf(m2 - mn);
            shm[t] = mn;
            shx[t] += shx[t + off];
        }
        __syncthreads();
    }
    if (t == 0) {
        float lse = shm[0] + logf(shs[0]);
        float sumx = shx[0];
        float la = row[answers[e]] - lse;
        float soft = (mask_type[e] > 0) ? 0.9f : 1.0f;
        float loss = -(soft * la +
                       (1.0f - soft) * (1.0f / (float)(VOCAB - 1)) *
                           ((sumx - (float)VOCAB * lse) - la));
        rowloss[e] = loss;
    }
}

__global__ void k_finalloss(const float* __restrict__ rowloss, float* __restrict__ out) {
    __shared__ float sh[256];
    float a = 0.0f;
    for (int i = threadIdx.x; i < E_EDGES; i += 256) a += rowloss[i];
    sh[threadIdx.x] = a;
    __syncthreads();
    for (int off = 128; off > 0; off >>= 1) {
        if (threadIdx.x < off) sh[threadIdx.x] += sh[threadIdx.x + off];
        __syncthreads();
    }
    if (threadIdx.x == 0) out[0] = sh[0] * (1.0f / (float)E_EDGES);
}

// ---------------- launch ----------------
extern "C" void kernel_launch(void* const* d_in, const int* in_sizes, int n_in,
                              void* d_out, int out_size) {
    const float* node_emb   = (const float*)d_in[0];
    const int*   input_ids  = (const int*)d_in[1];
    const float* input_mask = (const float*)d_in[2];
    const int*   edge_ord   = (const int*)d_in[3];
    const int*   vim        = (const int*)d_in[4];
    const int*   vibm       = (const int*)d_in[5];
    const int*   out_pos    = (const int*)d_in[6];
    const int*   lin        = (const int*)d_in[7];
    const int*   lib        = (const int*)d_in[8];
    const int*   ltypes     = (const int*)d_in[9];
    const int*   answers    = (const int*)d_in[10];
    const int*   mask_type  = (const int*)d_in[11];
    const float* W1         = (const float*)d_in[12];
    const float* b1         = (const float*)d_in[13];
    const float* W2         = (const float*)d_in[14];
    const float* b2         = (const float*)d_in[15];
    const float* ln_g       = (const float*)d_in[16];
    const float* ln_b       = (const float*)d_in[17];

    float* out = (float*)d_out;
    long long loff = (long long)out_size - (long long)E_EDGES * VOCAB;
    if (loff < 0) loff = 0;
    float* logits = out + loff;

    float *var0, *var1, *h, *hidden, *tmpC, *tmpD, *rowloss;
    __nv_bfloat16 *Ahi, *Alo, *Bhi, *Blo;
    cudaGetSymbolAddress((void**)&var0, g_var0);
    cudaGetSymbolAddress((void**)&var1, g_var1);
    cudaGetSymbolAddress((void**)&h, g_h);
    cudaGetSymbolAddress((void**)&hidden, g_hidden);
    cudaGetSymbolAddress((void**)&tmpC, g_tmpC);
    cudaGetSymbolAddress((void**)&tmpD, g_tmpD);
    cudaGetSymbolAddress((void**)&rowloss, g_rowloss);
    cudaGetSymbolAddress((void**)&Ahi, g_Ahi);
    cudaGetSymbolAddress((void**)&Alo, g_Alo);
    cudaGetSymbolAddress((void**)&Bhi, g_Bhi);
    cudaGetSymbolAddress((void**)&Blo, g_Blo);

    // host attribute set: idempotent, not a stream op, capture-safe
    cudaFuncSetAttribute(k_gemm_mma, cudaFuncAttributeMaxDynamicSharedMemorySize,
                         SMEM_GEMM);

    k_init<<<(E_EDGES * D) / 256, 256>>>(var0, var1);
    // pre-split node_emb into bf16 hi/lo (L2-resident B operand)
    k_split<<<(VOCAB * D + 255) / 256, 256>>>(node_emb, Bhi, Blo, VOCAB * D);

    for (int order = 0; order < NUM_ORDERS; ++order) {
        k_encoder<<<E_EDGES, 256>>>(node_emb, input_ids, input_mask, vim, vibm,
                                    out_pos, ln_g, ln_b, var1, h);
        k_mlp<<<E_EDGES / 16, 256>>>(h, W1, b1, hidden, 0);
        k_mlp<<<E_EDGES / 16, 256>>>(hidden, W2, b2, h, 1);
        k_update<<<E_EDGES, 256>>>(h, edge_ord, ltypes, order, var0, var1);
        k_conj<<<E_EDGES, 256>>>(var0, var1, edge_ord, ltypes, lin, lib, order, tmpC);
        k_disj<<<E_EDGES, 256>>>(var0, var1, edge_ord, ltypes, lin, lib, order, tmpC, tmpD);
        k_apply<<<E_EDGES, 256>>>(edge_ord, ltypes, order, tmpC, tmpD, var1);
    }

    k_split<<<(E_EDGES * D + 255) / 256, 256>>>(var1, Ahi, Alo, E_EDGES * D);

    dim3 grid((VOCAB + BNT - 1) / BNT, E_EDGES / BMT);
    k_gemm_mma<<<grid, 256, SMEM_GEMM>>>(Ahi, Alo, Bhi, Blo, logits);

    if (loff >= 1) {
        k_rowloss<<<E_EDGES, 256>>>(logits, answers, mask_type, rowloss);
        k_finalloss<<<1, 256>>>(rowloss, out);
    }
}